// round 6
// baseline (speedup 1.0000x reference)
#include <cuda_runtime.h>
#include <cstdint>

// Problem constants
#define BB   2
#define SS   2048
#define DIM  2048
#define NH   16
#define KVH  4
#define HD   128
#define ROWS (BB*SS)          // 4096
#define QKVD 3072             // fused Q|K|V width
#define KOFF 2048
#define VOFF 2560

// ---------------------------------------------------------------------------
// Scratch (static device globals — no allocation)
// ---------------------------------------------------------------------------
__device__ float gXr [(size_t)ROWS * DIM];    // X, tf32, K-permuted
__device__ float gWt [(size_t)QKVD * DIM];    // [Wq|Wk|Wv]^T, tf32, K-permuted
__device__ float gWot[(size_t)DIM * DIM];     // Wo^T, tf32, K-permuted
__device__ float gQKV[(size_t)ROWS * QKVD];   // Q,K d-permuted by rope; V normal
__device__ float gC  [(size_t)ROWS * DIM];    // attn ctx, tf32, K-permuted

// ---------------------------------------------------------------------------
// helpers
// ---------------------------------------------------------------------------
__device__ __forceinline__ unsigned tf32u(float x) {
    unsigned u;
    asm("cvt.rna.tf32.f32 %0, %1;" : "=r"(u) : "f"(x));
    return u;
}
__device__ __forceinline__ float tf32f(float x) { return __uint_as_float(tf32u(x)); }
__device__ __forceinline__ float ex2(float x) {
    float r;
    asm("ex2.approx.ftz.f32 %0, %1;" : "=f"(r) : "f"(x));
    return r;
}

// Permute X into gXr: within each 8-col group store {c0,c4,c1,c5,c2,c6,c3,c7}
__global__ void permute_round_x(const float* __restrict__ in,
                                float* __restrict__ out) {
    int idx = blockIdx.x * blockDim.x + threadIdx.x;   // one 8-group
    if (idx >= ROWS * (DIM / 8)) return;
    const float* s = in + (size_t)idx * 8;
    float4 v0 = *(const float4*)s;
    float4 v1 = *(const float4*)(s + 4);
    float* d = out + (size_t)idx * 8;
    *(float4*)d = make_float4(tf32f(v0.x), tf32f(v1.x), tf32f(v0.y), tf32f(v1.y));
    *(float4*)(d + 4) = make_float4(tf32f(v0.z), tf32f(v1.z), tf32f(v0.w), tf32f(v1.w));
}

// Transpose-pack all 4 weights: W[k][n] -> out[n][k_permuted], tf32.
// grid (64,64,4), block (32,8). z selects the weight.
__global__ void wpack_all(const float* __restrict__ wq,
                          const float* __restrict__ wk,
                          const float* __restrict__ wv,
                          const float* __restrict__ wo,
                          float* __restrict__ Wt, float* __restrict__ Wot) {
    const float* W;
    float* out;
    int Nw;
    int z = blockIdx.z;
    if (z == 0)      { W = wq; out = Wt;                         Nw = 2048; }
    else if (z == 1) { W = wo; out = Wot;                        Nw = 2048; }
    else if (z == 2) { W = wk; out = Wt + (size_t)2048 * 2048;   Nw = 512;  }
    else             { W = wv; out = Wt + (size_t)2560 * 2048;   Nw = 512;  }
    int n0 = blockIdx.x * 32;
    if (n0 >= Nw) return;

    __shared__ float t[32][33];
    int tx = threadIdx.x, ty = threadIdx.y;
    int k0 = blockIdx.y * 32;
    #pragma unroll
    for (int i = 0; i < 4; i++)
        t[ty + 8 * i][tx] = W[(size_t)(k0 + ty + 8 * i) * Nw + n0 + tx];
    __syncthreads();
    int grp = tx >> 3, pos = tx & 7;
    int ksrc = grp * 8 + ((pos >> 1) | ((pos & 1) << 2));
    #pragma unroll
    for (int i = 0; i < 4; i++)
        out[(size_t)(n0 + ty + 8 * i) * 2048 + k0 + tx] = tf32f(t[ksrc][ty + 8 * i]);
}

// ---------------------------------------------------------------------------
// TF32 GEMM v2 (R3, known-good): C[M,N] = A[M,K] @ Bt[N,K]^T, K-permuted.
// ---------------------------------------------------------------------------
#define GST 40
#define GEMM2_SMEM (2 * 2 * 128 * GST * 4)   // 81920 B

__device__ __forceinline__ void cp16(unsigned dst, const void* src) {
    asm volatile("cp.async.cg.shared.global [%0], [%1], 16;\n"
                 :: "r"(dst), "l"(src));
}

__device__ __forceinline__ void mma8(float* c, const unsigned* a,
                                     unsigned b0, unsigned b1) {
    asm volatile(
        "mma.sync.aligned.m16n8k8.row.col.f32.tf32.tf32.f32 "
        "{%0,%1,%2,%3}, {%4,%5,%6,%7}, {%8,%9}, {%0,%1,%2,%3};\n"
        : "+f"(c[0]), "+f"(c[1]), "+f"(c[2]), "+f"(c[3])
        : "r"(a[0]), "r"(a[1]), "r"(a[2]), "r"(a[3]), "r"(b0), "r"(b1));
}

__global__ __launch_bounds__(128) void tf32_gemm2(
    const float* __restrict__ A, const float* __restrict__ Bt,
    float* __restrict__ C, int N, int K)
{
    extern __shared__ float sm[];
    float* As = sm;                    // [2][128][GST]
    float* Bs = sm + 2 * 128 * GST;    // [2][128][GST]

    const int tid  = threadIdx.x;
    const int lane = tid & 31;
    const int w    = tid >> 5;
    const int g    = lane >> 2;
    const int l    = lane & 3;
    const int wm   = (w >> 1) * 64;
    const int wn   = (w & 1) * 64;
    const long bm  = (long)blockIdx.y * 128;
    const long bn  = (long)blockIdx.x * 128;

    const unsigned sAu = (unsigned)__cvta_generic_to_shared(As);
    const unsigned sBu = (unsigned)__cvta_generic_to_shared(Bs);

    const int frow = tid >> 3;
    const int fcol = (tid & 7) << 2;
    const float* Abase = A  + (bm + frow) * K + fcol;
    const float* Bbase = Bt + (bn + frow) * K + fcol;

    float acc[4][8][4];
    #pragma unroll
    for (int mt = 0; mt < 4; mt++)
        #pragma unroll
        for (int nt = 0; nt < 8; nt++)
            #pragma unroll
            for (int j = 0; j < 4; j++) acc[mt][nt][j] = 0.f;

    const int niter = K / 32;

    auto issue = [&](int it, int buf) {
        long k0 = (long)it * 32;
        #pragma unroll
        for (int p = 0; p < 8; p++)
            cp16(sAu + (unsigned)(((buf * 128 + frow + p * 16) * GST + fcol) * 4),
                 Abase + (long)p * 16 * K + k0);
        #pragma unroll
        for (int p = 0; p < 8; p++)
            cp16(sBu + (unsigned)(((buf * 128 + frow + p * 16) * GST + fcol) * 4),
                 Bbase + (long)p * 16 * K + k0);
        asm volatile("cp.async.commit_group;\n");
    };

    issue(0, 0);

    for (int it = 0; it < niter; it++) {
        const int buf = it & 1;
        if (it + 1 < niter) {
            issue(it + 1, buf ^ 1);
            asm volatile("cp.async.wait_group 1;\n");
        } else {
            asm volatile("cp.async.wait_group 0;\n");
        }
        __syncthreads();

        const float* Ab = As + buf * 128 * GST;
        const float* Bb = Bs + buf * 128 * GST;

        #pragma unroll
        for (int kk = 0; kk < 4; kk++) {
            float2 av[4][2];
            float2 bv[8];
            #pragma unroll
            for (int mt = 0; mt < 4; mt++) {
                av[mt][0] = *(const float2*)&Ab[(wm + mt * 16 + g)     * GST + kk * 8 + 2 * l];
                av[mt][1] = *(const float2*)&Ab[(wm + mt * 16 + g + 8) * GST + kk * 8 + 2 * l];
            }
            #pragma unroll
            for (int nt = 0; nt < 8; nt++)
                bv[nt] = *(const float2*)&Bb[(wn + nt * 8 + g) * GST + kk * 8 + 2 * l];

            #pragma unroll
            for (int mt = 0; mt < 4; mt++) {
                unsigned a[4];
                a[0] = __float_as_uint(av[mt][0].x);
                a[1] = __float_as_uint(av[mt][1].x);
                a[2] = __float_as_uint(av[mt][0].y);
                a[3] = __float_as_uint(av[mt][1].y);
                #pragma unroll
                for (int nt = 0; nt < 8; nt++)
                    mma8(acc[mt][nt], a,
                         __float_as_uint(bv[nt].x), __float_as_uint(bv[nt].y));
            }
        }
        __syncthreads();
    }

    #pragma unroll
    for (int mt = 0; mt < 4; mt++)
        #pragma unroll
        for (int nt = 0; nt < 8; nt++) {
            const float* c = acc[mt][nt];
            long row = bm + wm + mt * 16 + g;
            long col = bn + wn + nt * 8 + 2 * l;
            *(float2*)&C[row * N + col]       = make_float2(c[0], c[1]);
            *(float2*)&C[(row + 8) * N + col] = make_float2(c[2], c[3]);
        }
}

// ---------------------------------------------------------------------------
// RoPE in-place on Q/K, emitting d-PERMUTED layout: within each 8-group of d,
// physical order = logical {0,4,1,5,2,6,3,7}.  Each thread owns whole logical
// groups (t, t+8) of one (row, head) -> in-place permute is race-free.
// ---------------------------------------------------------------------------
__global__ void rope_kernel(float* __restrict__ x,
                            const float* __restrict__ cosT,
                            const float* __restrict__ sinT,
                            int nh_shift, int stride)
{
    int idx = blockIdx.x * blockDim.x + threadIdx.x;
    int nheads = 1 << nh_shift;
    int total = ROWS * nheads * 8;
    if (idx >= total) return;
    int t = idx & 7;                      // 8-group in [0,64)
    int h = (idx >> 3) & (nheads - 1);
    int r = idx >> (3 + nh_shift);
    int s = r & (SS - 1);

    const float* cs = cosT + s * HD + 8 * t;
    const float* sn = sinT + s * HD + 8 * t;
    float* p = x + (size_t)r * stride + h * HD + 8 * t;

    float a[8], bv[8];
    *(float4*)(a)      = *(const float4*)(p);
    *(float4*)(a + 4)  = *(const float4*)(p + 4);
    *(float4*)(bv)     = *(const float4*)(p + 64);
    *(float4*)(bv + 4) = *(const float4*)(p + 68);

    float oa[8], ob[8];
    #pragma unroll
    for (int j = 0; j < 8; j++) {
        float c0 = cs[j],      s0 = sn[j];
        float c1 = cs[64 + j], s1 = sn[64 + j];
        oa[j] = a[j] * c0 - bv[j] * s0;
        ob[j] = bv[j] * c1 + a[j] * s1;
    }
    float wa[8], wb[8];
    #pragma unroll
    for (int j = 0; j < 4; j++) {
        wa[2 * j] = oa[j];  wa[2 * j + 1] = oa[j + 4];
        wb[2 * j] = ob[j];  wb[2 * j + 1] = ob[j + 4];
    }
    *(float4*)(p)      = *(float4*)(wa);
    *(float4*)(p + 4)  = *(float4*)(wa + 4);
    *(float4*)(p + 64) = *(float4*)(wb);
    *(float4*)(p + 68) = *(float4*)(wb + 4);
}

// ---------------------------------------------------------------------------
// Tensor-core flash attention, Q-tile 128, 256 threads (8 warps x 16 rows).
// Q/K arrive d-permuted -> QK fragments are conflict-free LDS.64 (stride 136).
// ---------------------------------------------------------------------------
#define KST 136
#define VST 136
#define PST 68
#define ATTN_SMEM ((64*KST + 64*VST + 128*PST) * 4)   // 104448 B

__global__ __launch_bounds__(256) void attn_mma(
    const float* __restrict__ QKVg, const float* __restrict__ alibi,
    const float* __restrict__ amask, float* __restrict__ Og)
{
    extern __shared__ float smn[];
    float* sK = smn;                    // [64][136]
    float* sV = smn + 64 * KST;         // [64][136]
    float* sP = sV + 64 * VST;          // [128][68]
    float* sQ = smn;                    // [128][136] temp, spans sK+sV exactly

    const int tid  = threadIdx.x;
    const int lane = tid & 31;
    const int w    = tid >> 5;          // 0..7
    const int g    = lane >> 2;
    const int l    = lane & 3;
    const int bh   = blockIdx.y;
    const int b    = bh >> 4;
    const int h    = bh & 15;
    const int kvh  = h >> 2;
    const int bxr  = gridDim.x - 1 - blockIdx.x;   // heavy blocks first
    const int q0   = bxr * 128;
    const int ktiles = 2 * bxr + 2;

    // ---- stage Q tile (128 x 128) in smem, lift to registers ----
    for (int i = tid; i < 128 * 32; i += 256) {
        int r = i >> 5, c4 = (i & 31) << 2;
        *(float4*)&sQ[r * KST + c4] =
            *(const float4*)&QKVg[(size_t)(b * SS + q0 + r) * QKVD + h * HD + c4];
    }
    __syncthreads();

    unsigned qf[16][4];
    #pragma unroll
    for (int kc = 0; kc < 16; kc++) {
        float2 q0v = *(const float2*)&sQ[(w * 16 + g)     * KST + kc * 8 + 2 * l];
        float2 q1v = *(const float2*)&sQ[(w * 16 + g + 8) * KST + kc * 8 + 2 * l];
        qf[kc][0] = tf32u(q0v.x);
        qf[kc][1] = tf32u(q1v.x);
        qf[kc][2] = tf32u(q0v.y);
        qf[kc][3] = tf32u(q1v.y);
    }
    __syncthreads();

    const float L2E = 1.4426950408889634f;
    const float SCL = 0.08838834764831845f * L2E;   // 1/sqrt(128) * log2(e)

    float m0 = -1e30f, m1 = -1e30f, s0 = 0.f, s1 = 0.f;
    float o[16][4];
    #pragma unroll
    for (int i = 0; i < 16; i++)
        #pragma unroll
        for (int j = 0; j < 4; j++) o[i][j] = 0.f;

    const int qrow = q0 + w * 16 + g;

    for (int kt = 0; kt < ktiles; kt++) {
        const int k0 = kt * 64;

        // ---- cooperative load K (d-permuted), V (normal), tf32-rounded ----
        for (int i = tid; i < 64 * 32; i += 256) {
            int r = i >> 5, c4 = (i & 31) << 2;
            size_t rowbase = (size_t)(b * SS + k0 + r) * QKVD + kvh * HD + c4;
            float4 kv = *(const float4*)&QKVg[rowbase + KOFF];
            kv.x = tf32f(kv.x); kv.y = tf32f(kv.y);
            kv.z = tf32f(kv.z); kv.w = tf32f(kv.w);
            *(float4*)&sK[r * KST + c4] = kv;
            float4 vv = *(const float4*)&QKVg[rowbase + VOFF];
            vv.x = tf32f(vv.x); vv.y = tf32f(vv.y);
            vv.z = tf32f(vv.z); vv.w = tf32f(vv.w);
            *(float4*)&sV[r * VST + c4] = vv;
        }
        __syncthreads();

        // ---- QK^T: 16x64 per warp, B-frags via LDS.64 ----
        float sc[8][4];
        #pragma unroll
        for (int nb = 0; nb < 8; nb++)
            #pragma unroll
            for (int j = 0; j < 4; j++) sc[nb][j] = 0.f;

        #pragma unroll
        for (int kc = 0; kc < 16; kc++) {
            #pragma unroll
            for (int nb = 0; nb < 8; nb++) {
                float2 kv2 = *(const float2*)&sK[(nb * 8 + g) * KST + kc * 8 + 2 * l];
                mma8(sc[nb], qf[kc],
                     __float_as_uint(kv2.x), __float_as_uint(kv2.y));
            }
        }

        // ---- scale + alibi + mask + causal (log2 domain) ----
        const bool diag = (k0 + 63 > qrow);
        float mx0 = -1e30f, mx1 = -1e30f;
        {
            const float* alr = &alibi[((size_t)b * SS + qrow) * SS + k0 + 2 * l];
            const float* amr = &amask[b * SS + k0 + 2 * l];
            #pragma unroll
            for (int nb = 0; nb < 8; nb++) {
                float2 amv = *(const float2*)(amr + nb * 8);
                float2 al0 = *(const float2*)(alr + nb * 8);
                float2 al1 = *(const float2*)(alr + nb * 8 + 8 * SS);
                sc[nb][0] = sc[nb][0] * SCL + (al0.x + amv.x) * L2E;
                sc[nb][1] = sc[nb][1] * SCL + (al0.y + amv.y) * L2E;
                sc[nb][2] = sc[nb][2] * SCL + (al1.x + amv.x) * L2E;
                sc[nb][3] = sc[nb][3] * SCL + (al1.y + amv.y) * L2E;
                if (diag) {
                    int kc0 = k0 + nb * 8 + 2 * l;
                    if (kc0     > qrow)     sc[nb][0] += -1e9f * L2E;
                    if (kc0 + 1 > qrow)     sc[nb][1] += -1e9f * L2E;
                    if (kc0     > qrow + 8) sc[nb][2] += -1e9f * L2E;
                    if (kc0 + 1 > qrow + 8) sc[nb][3] += -1e9f * L2E;
                }
                mx0 = fmaxf(mx0, fmaxf(sc[nb][0], sc[nb][1]));
                mx1 = fmaxf(mx1, fmaxf(sc[nb][2], sc[nb][3]));
            }
        }

        mx0 = fmaxf(mx0, __shfl_xor_sync(0xffffffffu, mx0, 1));
        mx0 = fmaxf(mx0, __shfl_xor_sync(0xffffffffu, mx0, 2));
        mx1 = fmaxf(mx1, __shfl_xor_sync(0xffffffffu, mx1, 1));
        mx1 = fmaxf(mx1, __shfl_xor_sync(0xffffffffu, mx1, 2));

        float mn0 = fmaxf(m0, mx0), mn1 = fmaxf(m1, mx1);
        float c0 = ex2(m0 - mn0), c1 = ex2(m1 - mn1);
        m0 = mn0; m1 = mn1;

        // ---- p = 2^(sc - m), row sums, store P (tf32) ----
        float rs0 = 0.f, rs1 = 0.f;
        #pragma unroll
        for (int nb = 0; nb < 8; nb++) {
            float p00 = ex2(sc[nb][0] - m0);
            float p01 = ex2(sc[nb][1] - m0);
            float p10 = ex2(sc[nb][2] - m1);
            float p11 = ex2(sc[nb][3] - m1);
            rs0 += p00 + p01;
            rs1 += p10 + p11;
            *(float2*)&sP[(w * 16 + g)     * PST + nb * 8 + 2 * l] =
                make_float2(tf32f(p00), tf32f(p01));
            *(float2*)&sP[(w * 16 + g + 8) * PST + nb * 8 + 2 * l] =
                make_float2(tf32f(p10), tf32f(p11));
        }
        rs0 += __shfl_xor_sync(0xffffffffu, rs0, 1);
        rs0 += __shfl_xor_sync(0xffffffffu, rs0, 2);
        rs1 += __shfl_xor_sync(0xffffffffu, rs1, 1);
        rs1 += __shfl_xor_sync(0xffffffffu, rs1, 2);
        s0 = s0 * c0 + rs0;
        s1 = s1 * c1 + rs1;

        #pragma unroll
        for (int nb = 0; nb < 16; nb++) {
            o[nb][0] *= c0; o[nb][1] *= c0;
            o[nb][2] *= c1; o[nb][3] *= c1;
        }
        __syncwarp();

        // ---- O += P @ V ----
        #pragma unroll
        for (int kc = 0; kc < 8; kc++) {
            unsigned a[4];
            a[0] = __float_as_uint(sP[(w * 16 + g)     * PST + kc * 8 + l]);
            a[1] = __float_as_uint(sP[(w * 16 + g + 8) * PST + kc * 8 + l]);
            a[2] = __float_as_uint(sP[(w * 16 + g)     * PST + kc * 8 + l + 4]);
            a[3] = __float_as_uint(sP[(w * 16 + g + 8) * PST + kc * 8 + l + 4]);
            #pragma unroll
            for (int nb = 0; nb < 16; nb++) {
                unsigned b0 = __float_as_uint(sV[(kc * 8 + l)     * VST + nb * 8 + g]);
                unsigned b1 = __float_as_uint(sV[(kc * 8 + l + 4) * VST + nb * 8 + g]);
                mma8(o[nb], a, b0, b1);
            }
        }
        __syncthreads();
    }

    // ---- epilogue: O /= l, tf32-round, write K-PERMUTED ctx for Wo GEMM ----
    float inv0 = 1.0f / s0, inv1 = 1.0f / s1;
    size_t row0 = (size_t)(b * SS + qrow);
    const int pos0 = (l < 2) ? 4 * l : 4 * l - 7;
    #pragma unroll
    for (int nb = 0; nb < 16; nb++) {
        size_t cb = h * HD + nb * 8;
        Og[row0 * DIM + cb + pos0]           = tf32f(o[nb][0] * inv0);
        Og[row0 * DIM + cb + pos0 + 2]       = tf32f(o[nb][1] * inv0);
        Og[(row0 + 8) * DIM + cb + pos0]     = tf32f(o[nb][2] * inv1);
        Og[(row0 + 8) * DIM + cb + pos0 + 2] = tf32f(o[nb][3] * inv1);
    }
}

// ---------------------------------------------------------------------------
// Launch  (order chosen so launch #6 = attn_mma for ncu -s 5 -c 1)
// ---------------------------------------------------------------------------
extern "C" void kernel_launch(void* const* d_in, const int* in_sizes, int n_in,
                              void* d_out, int out_size)
{
    const float* X     = (const float*)d_in[0];
    const float* cosT  = (const float*)d_in[1];
    const float* sinT  = (const float*)d_in[2];
    const float* alibi = (const float*)d_in[3];
    const float* amask = (const float*)d_in[4];
    const float* wq    = (const float*)d_in[5];
    const float* wk    = (const float*)d_in[6];
    const float* wv    = (const float*)d_in[7];
    const float* wo    = (const float*)d_in[8];
    float* out = (float*)d_out;

    float *Xr, *Wt, *Wot, *QKV, *C;
    cudaGetSymbolAddress((void**)&Xr,  gXr);
    cudaGetSymbolAddress((void**)&Wt,  gWt);
    cudaGetSymbolAddress((void**)&Wot, gWot);
    cudaGetSymbolAddress((void**)&QKV, gQKV);
    cudaGetSymbolAddress((void**)&C,   gC);

    cudaFuncSetAttribute(tf32_gemm2,
                         cudaFuncAttributeMaxDynamicSharedMemorySize, GEMM2_SMEM);
    cudaFuncSetAttribute(attn_mma,
                         cudaFuncAttributeMaxDynamicSharedMemorySize, ATTN_SMEM);

    // 1: permute+round X
    permute_round_x<<<ROWS * (DIM / 8) / 256, 256>>>(X, Xr);
    // 2: all weight packs
    wpack_all<<<dim3(64, 64, 4), dim3(32, 8)>>>(wq, wk, wv, wo, Wt, Wot);
    // 3: fused QKV projection
    tf32_gemm2<<<dim3(QKVD / 128, ROWS / 128), 128, GEMM2_SMEM>>>(
        Xr, Wt, QKV, QKVD, DIM);
    // 4,5: RoPE on Q (16 heads) and K (4 heads) — emits d-permuted layout
    rope_kernel<<<(ROWS * NH * 8 + 255) / 256, 256>>>(QKV, cosT, sinT, 4, QKVD);
    rope_kernel<<<(ROWS * KVH * 8 + 255) / 256, 256>>>(QKV + KOFF, cosT, sinT, 2, QKVD);
    // 6: tensor-core flash attention (profiled by ncu -s 5 -c 1)
    attn_mma<<<dim3(SS / 128, BB * NH), 256, ATTN_SMEM>>>(QKV, alibi, amask, C);
    // 7: output projection
    tf32_gemm2<<<dim3(DIM / 128, ROWS / 128), 128, GEMM2_SMEM>>>(
        C, Wot, out, DIM, DIM);
}